// round 11
// baseline (speedup 1.0000x reference)
#include <cuda_runtime.h>
#include <cuda_bf16.h>

#define NPTS  16384
#define NNBR  32
#define CIN   16
#define COUT  16
#define NB    16
#define GAMMA 10.0f
#define EPSF  1e-12f

// Scratch (allocation-free rule: __device__ globals)
__device__ float4 g_inputT[NPTS * 4];        // [n*4+q] : channels 4q..4q+3 of point n
__device__ float4 g_coords4[NPTS];           // padded coords
__device__ float  g_U[NPTS * NNBR * NB];     // 32MB; per point: [jj][k][c] (512 floats)

// ---------------- f32x2 helpers (sm_103a packed fp32) ----------------------
__device__ __forceinline__ unsigned long long ffma2(unsigned long long a,
                                                    unsigned long long b,
                                                    unsigned long long c) {
    unsigned long long d;
    asm("fma.rn.f32x2 %0, %1, %2, %3;" : "=l"(d) : "l"(a), "l"(b), "l"(c));
    return d;
}
__device__ __forceinline__ unsigned long long dup2(float x) {
    unsigned long long d;
    asm("mov.b64 %0, {%1, %1};" : "=l"(d) : "f"(x));
    return d;
}
__device__ __forceinline__ float2 unpack2(unsigned long long v) {
    float2 f;
    asm("mov.b64 {%0, %1}, %2;" : "=f"(f.x), "=f"(f.y) : "l"(v));
    return f;
}

// ---------------------------------------------------------------------------
// Prep: transpose input (C,N)->(N,C) float4 rows; pad coords to float4.
// ---------------------------------------------------------------------------
__global__ void prep_kernel(const float* __restrict__ input,
                            const float* __restrict__ coords) {
    int idx = blockIdx.x * blockDim.x + threadIdx.x;   // 0 .. NPTS*4-1
    int q = idx >> 14;            // idx / NPTS
    int n = idx & (NPTS - 1);
    float4 v;
    v.x = input[(4 * q + 0) * NPTS + n];
    v.y = input[(4 * q + 1) * NPTS + n];
    v.z = input[(4 * q + 2) * NPTS + n];
    v.w = input[(4 * q + 3) * NPTS + n];
    g_inputT[n * 4 + q] = v;
    if (q == 0) {
        float4 c;
        c.x = coords[n * 3 + 0];
        c.y = coords[n * 3 + 1];
        c.z = coords[n * 3 + 2];
        c.w = 0.0f;
        g_coords4[n] = c;
    }
}

// ---------------------------------------------------------------------------
// Phase A: u[n,k,b] = mask * exp(-g (r-c_b)^2), zero exp redundancy.
// One thread per (n,k); warp = one point, lane = neighbor.
//   arg_b = NGL2*r^2 + log2(m) + r*(-2 NGL2 c_b) + NGL2 c_b^2
// ---------------------------------------------------------------------------
__global__ __launch_bounds__(256)
void rbf_kernel(const float* __restrict__ centers,
                const float* __restrict__ mask,
                const int*   __restrict__ neighbors) {
    const int tid = threadIdx.x;
    const int n = blockIdx.x * 8 + (tid >> 5);
    const int k = tid & 31;

    const float NGL2 = -GAMMA * 1.4426950408889634f;
    const int   nbr = __ldg(&neighbors[n * NNBR + k]);
    const float m   = __ldg(&mask[n * NNBR + k]);
    const float4 pc = g_coords4[n];
    const float4 cc = g_coords4[nbr];
    const float dx = cc.x - pc.x;
    const float dy = cc.y - pc.y;
    const float dz = cc.z - pc.z;
    const float r2 = fmaf(dx, dx, fmaf(dy, dy, fmaf(dz, dz, EPSF)));
    const float r  = sqrtf(r2);
    const float e0 = fmaf(NGL2, r2, __log2f(m));

    float4* Ur = (float4*)(g_U + (size_t)n * 512);
    #pragma unroll
    for (int jj = 0; jj < 4; jj++) {
        float u[4];
        #pragma unroll
        for (int c = 0; c < 4; c++) {
            const float cb = __ldg(&centers[4 * jj + c]);
            const float cs = -2.0f * NGL2 * cb;
            const float K  = NGL2 * cb * cb;
            u[c] = exp2f(fmaf(r, cs, e0 + K));
        }
        Ur[jj * 32 + k] = make_float4(u[0], u[1], u[2], u[3]);
    }
}

// ---------------------------------------------------------------------------
// Phase B: pure contraction, no transcendentals.
// 8 lanes/point: t = channel quartet (4t..4t+3), h = neighbor half (16 nbrs).
// acc[bp][c] : f32x2 over basis pair (2bp,2bp+1) for channel 4t+c. 32 FFMA2/nbr.
// U staged in smem (point stride 516 floats to break conflicts), W as u64 pairs.
// Epilogue: FFMA2 W-contraction, width-8 butterfly, lane writes outputs 2l,2l+1.
// (Audited R10: staging = 16 iters x 256 thr = 4096 float4 = exact slab;
//  smem indices bounded; acc/W/epilogue maps consistent.)
// ---------------------------------------------------------------------------
#define CONV_SMEM (32 * 516 * 4 + COUT * CIN * 8 * 8)   // 66048 + 16384 = 82432 B

__global__ __launch_bounds__(256, 2)
void conv_kernel(const float* __restrict__ Wmat,
                 const int*   __restrict__ neighbors,
                 float*       __restrict__ out) {
    extern __shared__ char smem[];
    float* sm_U = (float*)smem;                                   // 32 pts x 516 floats
    unsigned long long* sm_W = (unsigned long long*)(smem + 32 * 516 * 4);

    const int tid = threadIdx.x;

    // Stage U: block slab = 32 pts * 128 float4 = 4096 float4 (16 iters x 256 thr).
    {
        const float4* Ug = (const float4*)(g_U + (size_t)blockIdx.x * (32 * 512));
        float4* Us4 = (float4*)sm_U;
        #pragma unroll
        for (int i = 0; i < 16; i++) {
            const int idx = tid + 256 * i;
            const int pt = idx >> 7;          // 128 float4 per point
            const int w  = idx & 127;
            Us4[pt * 129 + w] = Ug[idx];
        }
    }
    // Stage W as u64 (basis-pairs contiguous): 2048 entries.
    {
        const unsigned long long* Wg = (const unsigned long long*)Wmat;
        #pragma unroll
        for (int i = 0; i < 8; i++)
            sm_W[tid + 256 * i] = Wg[tid + 256 * i];
    }
    __syncthreads();

    const int lane8 = tid & 7;
    const int t  = lane8 & 3;       // channel quartet
    const int h  = lane8 >> 2;      // neighbor half
    const int pl = tid >> 3;        // point within block (0..31)
    const int n  = blockIdx.x * 32 + pl;

    unsigned long long acc[8][4];
    #pragma unroll
    for (int bp = 0; bp < 8; bp++)
        #pragma unroll
        for (int c = 0; c < 4; c++) acc[bp][c] = 0ull;

    const int4* nb4 = (const int4*)(neighbors + n * NNBR + h * 16);
    const ulonglong2* Up = (const ulonglong2*)(sm_U + pl * 516);

    for (int kk = 0; kk < 4; kk++) {
        const int4 nb = __ldg(&nb4[kk]);
        const int ns[4] = {nb.x, nb.y, nb.z, nb.w};
        #pragma unroll
        for (int j = 0; j < 4; j++) {
            const int k = h * 16 + kk * 4 + j;
            const float4 xq = __ldg(&g_inputT[ns[j] * 4 + t]);
            unsigned long long xd[4];
            xd[0] = dup2(xq.x); xd[1] = dup2(xq.y);
            xd[2] = dup2(xq.z); xd[3] = dup2(xq.w);
            #pragma unroll
            for (int jj = 0; jj < 4; jj++) {
                const ulonglong2 up = Up[jj * 32 + k];   // (u4jj,u4jj+1),(u4jj+2,u4jj+3)
                #pragma unroll
                for (int c = 0; c < 4; c++) {
                    acc[2 * jj + 0][c] = ffma2(up.x, xd[c], acc[2 * jj + 0][c]);
                    acc[2 * jj + 1][c] = ffma2(up.y, xd[c], acc[2 * jj + 1][c]);
                }
            }
        }
    }

    // Epilogue: po[o] = sum_{c,bp} W2[o][4t+c][bp] . acc[bp][c], reduce 8 lanes.
    float po0 = 0.f, po1 = 0.f;
    #pragma unroll
    for (int o = 0; o < COUT; o++) {
        unsigned long long s2 = 0ull;
        #pragma unroll
        for (int c = 0; c < 4; c++) {
            const unsigned long long* wr = sm_W + (o * CIN + 4 * t + c) * 8;
            #pragma unroll
            for (int bp = 0; bp < 8; bp++)
                s2 = ffma2(wr[bp], acc[bp][c], s2);
        }
        const float2 sf = unpack2(s2);
        float s = sf.x + sf.y;
        s += __shfl_xor_sync(0xFFFFFFFFu, s, 1, 8);
        s += __shfl_xor_sync(0xFFFFFFFFu, s, 2, 8);
        s += __shfl_xor_sync(0xFFFFFFFFu, s, 4, 8);
        if ((o >> 1) == lane8) { if (o & 1) po1 = s; else po0 = s; }
    }
    out[(2 * lane8 + 0) * NPTS + n] = po0;
    out[(2 * lane8 + 1) * NPTS + n] = po1;
}

// ---------------------------------------------------------------------------
extern "C" void kernel_launch(void* const* d_in, const int* in_sizes, int n_in,
                              void* d_out, int out_size) {
    const float* input     = (const float*)d_in[0];   // (16, 16384)
    const float* coords    = (const float*)d_in[1];   // (16384, 3)
    const float* W         = (const float*)d_in[2];   // (16, 16, 16)
    const float* centers   = (const float*)d_in[3];   // (16,)
    const float* mask      = (const float*)d_in[4];   // (16384, 32)
    const int*   neighbors = (const int*)d_in[5];     // (16384, 32)
    float*       out       = (float*)d_out;           // (16, 16384)

    // Idempotent, not stream-associated: safe to call every time (no static guard).
    cudaFuncSetAttribute(conv_kernel,
                         cudaFuncAttributeMaxDynamicSharedMemorySize, CONV_SMEM);

    prep_kernel<<<(NPTS * 4) / 256, 256>>>(input, coords);
    rbf_kernel<<<NPTS / 8, 256>>>(centers, mask, neighbors);
    conv_kernel<<<NPTS / 32, 256, CONV_SMEM>>>(W, neighbors, out);
}

// round 12
// speedup vs baseline: 2.4251x; 2.4251x over previous
#include <cuda_runtime.h>
#include <cuda_bf16.h>

#define NPTS  16384
#define NNBR  32
#define CIN   16
#define COUT  16
#define NB    16
#define GAMMA 10.0f
#define EPSF  1e-12f

// Scratch (allocation-free rule: __device__ globals)
__device__ float4     g_inputT[NPTS * 4];   // [n*4+q] : channels 4q..4q+3 of point n
__device__ float4     g_coords4[NPTS];      // padded coords
__device__ ulonglong2 g_Wt2v[1024];         // W repacked: entry (o*16+b)*4+c2 =
                                            // ((W[o][4c2][b],W[o][4c2+1][b]),(W[o][4c2+2][b],W[o][4c2+3][b]))

// ---------------- f32x2 helpers (sm_103a packed fp32) ----------------------
__device__ __forceinline__ unsigned long long ffma2(unsigned long long a,
                                                    unsigned long long b,
                                                    unsigned long long c) {
    unsigned long long d;
    asm("fma.rn.f32x2 %0, %1, %2, %3;" : "=l"(d) : "l"(a), "l"(b), "l"(c));
    return d;
}
__device__ __forceinline__ unsigned long long dup2(float x) {
    unsigned long long d;
    asm("mov.b64 %0, {%1, %1};" : "=l"(d) : "f"(x));
    return d;
}
__device__ __forceinline__ unsigned long long pack2(float lo, float hi) {
    unsigned long long d;
    asm("mov.b64 %0, {%1, %2};" : "=l"(d) : "f"(lo), "f"(hi));
    return d;
}
__device__ __forceinline__ float2 unpack2(unsigned long long v) {
    float2 f;
    asm("mov.b64 {%0, %1}, %2;" : "=f"(f.x), "=f"(f.y) : "l"(v));
    return f;
}
__device__ __forceinline__ float ex2(float x) {
    float y;
    asm("ex2.approx.ftz.f32 %0, %1;" : "=f"(y) : "f"(x));
    return y;
}

// ---------------------------------------------------------------------------
// Prep: transpose input (C,N)->(N,C) float4 rows; pad coords; repack W into
// channel-pair u64s for the FFMA2 epilogue.
// ---------------------------------------------------------------------------
__global__ void prep_kernel(const float* __restrict__ input,
                            const float* __restrict__ coords,
                            const float* __restrict__ W) {
    int idx = blockIdx.x * blockDim.x + threadIdx.x;   // 0 .. NPTS*4-1
    int q = idx >> 14;            // idx / NPTS
    int n = idx & (NPTS - 1);
    float4 v;
    v.x = input[(4 * q + 0) * NPTS + n];
    v.y = input[(4 * q + 1) * NPTS + n];
    v.z = input[(4 * q + 2) * NPTS + n];
    v.w = input[(4 * q + 3) * NPTS + n];
    g_inputT[n * 4 + q] = v;
    if (q == 0) {
        float4 c;
        c.x = coords[n * 3 + 0];
        c.y = coords[n * 3 + 1];
        c.z = coords[n * 3 + 2];
        c.w = 0.0f;
        g_coords4[n] = c;
    }
    if (idx < 1024) {
        const int row = idx >> 2;        // o*16 + b
        const int c2  = idx & 3;
        const int o = row >> 4, b = row & 15;
        ulonglong2 w2;
        w2.x = pack2(W[(o * 16 + 4 * c2 + 0) * 16 + b], W[(o * 16 + 4 * c2 + 1) * 16 + b]);
        w2.y = pack2(W[(o * 16 + 4 * c2 + 2) * 16 + b], W[(o * 16 + 4 * c2 + 3) * 16 + b]);
        g_Wt2v[idx] = w2;
    }
}

// ---------------------------------------------------------------------------
// Main: 4 lanes/point (R0 partition). Lane t owns bases 4t..4t+3.
// acc2[bb][cp] (f32x2) = (A[ch 2cp][4t+bb], A[ch 2cp+1][4t+bb]).
// Per neighbor quad: lane t computes r,e0 for neighbor 4kk+t only (no
// redundancy), shuffled to the group. Per neighbor: 4 EX2 (own bases),
// x distributed as packed u64 shuffles, 32 FFMA2.
// Epilogue: FFMA2 against channel-pair W (smem, 2-way-conflict worst case),
// width-4 butterfly, lane t writes outputs 4t..4t+3.
// ---------------------------------------------------------------------------
__global__ __launch_bounds__(256, 2)
void conv_kernel(const float* __restrict__ centers,
                 const float* __restrict__ mask,
                 const int*   __restrict__ neighbors,
                 float*       __restrict__ out) {
    __shared__ ulonglong2 smWt[COUT * CIN * 5];   // row pad 5 to break t-conflicts (20.5KB)

    const int tid = threadIdx.x;
    #pragma unroll
    for (int e = 0; e < 4; e++) {
        const int gi = tid + 256 * e;
        smWt[(gi >> 2) * 5 + (gi & 3)] = g_Wt2v[gi];
    }
    __syncthreads();

    const int t  = tid & 3;          // basis-quartet owner
    const int pl = tid >> 2;         // point within block (0..63)
    const int n  = blockIdx.x * 64 + pl;

    const float NGL2 = -GAMMA * 1.4426950408889634f;
    float cs[4], K[4];
    #pragma unroll
    for (int bb = 0; bb < 4; bb++) {
        const float cb = __ldg(&centers[4 * t + bb]);
        cs[bb] = -2.0f * NGL2 * cb;
        K[bb]  = NGL2 * cb * cb;
    }
    const float4 pc = g_coords4[n];

    unsigned long long acc2[4][8];
    #pragma unroll
    for (int bb = 0; bb < 4; bb++)
        #pragma unroll
        for (int cp = 0; cp < 8; cp++) acc2[bb][cp] = 0ull;

    const int4*  nb4 = (const int4*)(neighbors + n * NNBR);
    const float* mkp = mask + n * NNBR;
    const ulonglong2* inT = (const ulonglong2*)g_inputT;

    // Pipeline: own-neighbor (k = 4*kk + t) index/mask/coords one quad ahead.
    int4  nb   = __ldg(&nb4[0]);
    float mown = __ldg(&mkp[t]);
    int   nown = (t == 0) ? nb.x : (t == 1) ? nb.y : (t == 2) ? nb.z : nb.w;
    float4 cc  = __ldg(&g_coords4[nown]);

    #pragma unroll 2
    for (int kk = 0; kk < 8; kk++) {
        const float dx = cc.x - pc.x;
        const float dy = cc.y - pc.y;
        const float dz = cc.z - pc.z;
        const float r2 = fmaf(dx, dx, fmaf(dy, dy, fmaf(dz, dz, EPSF)));
        const float r_own  = sqrtf(r2);
        const float e0_own = fmaf(NGL2, r2, __log2f(mown));
        const int4 nbc = nb;
        if (kk < 7) {
            nb   = __ldg(&nb4[kk + 1]);
            mown = __ldg(&mkp[(kk + 1) * 4 + t]);
            nown = (t == 0) ? nb.x : (t == 1) ? nb.y : (t == 2) ? nb.z : nb.w;
            cc   = __ldg(&g_coords4[nown]);
        }

        #pragma unroll
        for (int j = 0; j < 4; j++) {
            const float r  = __shfl_sync(0xFFFFFFFFu, r_own,  j, 4);
            const float e0 = __shfl_sync(0xFFFFFFFFu, e0_own, j, 4);
            const int  nbj = (j == 0) ? nbc.x : (j == 1) ? nbc.y : (j == 2) ? nbc.z : nbc.w;
            const ulonglong2 X = __ldg(&inT[nbj * 4 + t]);   // own channel quartet as 2 pairs

            unsigned long long ud[4];
            #pragma unroll
            for (int bb = 0; bb < 4; bb++)
                ud[bb] = dup2(ex2(fmaf(r, cs[bb], e0 + K[bb])));

            #pragma unroll
            for (int q = 0; q < 4; q++) {
                const unsigned long long xp0 = __shfl_sync(0xFFFFFFFFu, X.x, q, 4); // (x4q,  x4q+1)
                const unsigned long long xp1 = __shfl_sync(0xFFFFFFFFu, X.y, q, 4); // (x4q+2,x4q+3)
                #pragma unroll
                for (int bb = 0; bb < 4; bb++) {
                    acc2[bb][2 * q + 0] = ffma2(ud[bb], xp0, acc2[bb][2 * q + 0]);
                    acc2[bb][2 * q + 1] = ffma2(ud[bb], xp1, acc2[bb][2 * q + 1]);
                }
            }
        }
    }

    // Epilogue: s(o) = sum_{bb,cp} W2[o][4t+bb][cp] . acc2[bb][cp]
    float po[4];
    #pragma unroll
    for (int o = 0; o < COUT; o++) {
        unsigned long long s2 = 0ull;
        #pragma unroll
        for (int bb = 0; bb < 4; bb++) {
            const ulonglong2* wr = &smWt[(o * CIN + 4 * t + bb) * 5];
            #pragma unroll
            for (int c2 = 0; c2 < 4; c2++) {
                const ulonglong2 w2 = wr[c2];
                s2 = ffma2(w2.x, acc2[bb][2 * c2 + 0], s2);
                s2 = ffma2(w2.y, acc2[bb][2 * c2 + 1], s2);
            }
        }
        const float2 sf = unpack2(s2);
        float s = sf.x + sf.y;
        s += __shfl_xor_sync(0xFFFFFFFFu, s, 1, 4);
        s += __shfl_xor_sync(0xFFFFFFFFu, s, 2, 4);
        if ((o >> 2) == t) po[o & 3] = s;
    }

    #pragma unroll
    for (int j = 0; j < 4; j++)
        out[(4 * t + j) * NPTS + n] = po[j];
}

// ---------------------------------------------------------------------------
extern "C" void kernel_launch(void* const* d_in, const int* in_sizes, int n_in,
                              void* d_out, int out_size) {
    const float* input     = (const float*)d_in[0];   // (16, 16384)
    const float* coords    = (const float*)d_in[1];   // (16384, 3)
    const float* W         = (const float*)d_in[2];   // (16, 16, 16)
    const float* centers   = (const float*)d_in[3];   // (16,)
    const float* mask      = (const float*)d_in[4];   // (16384, 32)
    const int*   neighbors = (const int*)d_in[5];     // (16384, 32)
    float*       out       = (float*)d_out;           // (16, 16384)

    prep_kernel<<<(NPTS * 4) / 256, 256>>>(input, coords, W);
    conv_kernel<<<NPTS / 64, 256>>>(centers, mask, neighbors, out);
}